// round 7
// baseline (speedup 1.0000x reference)
#include <cuda_runtime.h>

#define N_MAX 50000
#define E_MAX 800000
#define HD 128
#define NH 8

// ---- scratch (device globals; no allocation allowed) ----
__device__ float g_hf[N_MAX * HD];      // nfeat @ W_fc
__device__ float g_el[N_MAX * NH];
__device__ float g_er[N_MAX * NH];
__device__ float g_Sagg[N_MAX * HD];    // segment_sum(efeat)
__device__ float g_invm[N_MAX];         // 1/max(deg,1)
__device__ int   g_cnt[N_MAX];          // dst histogram
__device__ int   g_off[N_MAX + 1];      // CSR offsets (immutable)
__device__ int   g_cur[N_MAX];          // mutable cursor for permute
__device__ int2  g_pse[E_MAX];          // (src, edge_id) grouped by dst

// packed f32x2 helpers (FFMA2 — PTX-only path on sm_103a)
__device__ __forceinline__ unsigned long long pack2(float lo, float hi) {
    unsigned long long r;
    asm("mov.b64 %0, {%1, %2};" : "=l"(r) : "r"(__float_as_uint(lo)), "r"(__float_as_uint(hi)));
    return r;
}
__device__ __forceinline__ void fma2(unsigned long long& acc, unsigned long long a, unsigned long long b) {
    asm("fma.rn.f32x2 %0, %1, %2, %0;" : "+l"(acc) : "l"(a), "l"(b));
}
__device__ __forceinline__ void unpack2(unsigned long long v, float& lo, float& hi) {
    unsigned int l, h;
    asm("mov.b64 {%0, %1}, %2;" : "=r"(l), "=r"(h) : "l"(v));
    lo = __uint_as_float(l); hi = __uint_as_float(h);
}

__device__ __forceinline__ float leaky02(float x) { return x > 0.f ? x : 0.2f * x; }

// ---------------- GEMM: 128x128 block tile, 8x8 per thread ----------------
// mode 0: out = A@W, plus el/er head reductions.
// mode 1: fused finalize: out[row] += (A@W)[row] * g_invm[row]   (out preloaded)
#define KC 32
__global__ __launch_bounds__(256, 2)
void gemm_kernel(const float* __restrict__ A, const float* __restrict__ W,
                 float* __restrict__ out, int nrows, int mode,
                 const float* __restrict__ attn_l, const float* __restrict__ attn_r) {
    __shared__ float Ws[KC][128];
    __shared__ float As[128][KC + 4];
    int t = threadIdx.x;
    int tx = t & 15;
    int ty = t >> 4;
    int rbase = blockIdx.x * 128;

    unsigned long long acc[8][4];
#pragma unroll
    for (int i = 0; i < 8; i++)
#pragma unroll
        for (int j = 0; j < 4; j++) acc[i][j] = 0ull;

    for (int kc = 0; kc < 4; kc++) {
#pragma unroll
        for (int i = 0; i < 4; i++) {
            int lin = i * 256 + t;
            int r = lin >> 5, c4 = lin & 31;
            *((float4*)&Ws[r][c4 * 4]) = ((const float4*)W)[(kc * 32 + r) * 32 + c4];
        }
#pragma unroll
        for (int i = 0; i < 4; i++) {
            int lin = i * 256 + t;
            int r = lin >> 3, k4 = lin & 7;
            int row = rbase + r;
            float4 v = (row < nrows) ? ((const float4*)A)[(size_t)row * 32 + kc * 8 + k4]
                                     : make_float4(0.f, 0.f, 0.f, 0.f);
            *((float4*)&As[r][k4 * 4]) = v;
        }
        __syncthreads();
#pragma unroll
        for (int k = 0; k < KC; k++) {
            unsigned long long w2[4];
#pragma unroll
            for (int j = 0; j < 4; j++)
                w2[j] = *(const unsigned long long*)&Ws[k][tx * 8 + j * 2];
#pragma unroll
            for (int i = 0; i < 8; i++) {
                float a = As[ty * 8 + i][k];
                unsigned long long aa = pack2(a, a);
#pragma unroll
                for (int j = 0; j < 4; j++) fma2(acc[i][j], aa, w2[j]);
            }
        }
        __syncthreads();
    }

    float al[8], ar[8];
    if (mode == 0) {
#pragma unroll
        for (int j = 0; j < 8; j++) { al[j] = attn_l[tx * 8 + j]; ar[j] = attn_r[tx * 8 + j]; }
    }

#pragma unroll
    for (int i = 0; i < 8; i++) {
        int row = rbase + ty * 8 + i;
        float c[8];
#pragma unroll
        for (int j = 0; j < 4; j++) unpack2(acc[i][j], c[2 * j], c[2 * j + 1]);
        if (mode == 0) {
            if (row < nrows) {
                *(float4*)&out[(size_t)row * 128 + tx * 8]     = make_float4(c[0], c[1], c[2], c[3]);
                *(float4*)&out[(size_t)row * 128 + tx * 8 + 4] = make_float4(c[4], c[5], c[6], c[7]);
            }
            float pl = 0.f, pr = 0.f;
#pragma unroll
            for (int j = 0; j < 8; j++) { pl += c[j] * al[j]; pr += c[j] * ar[j]; }
            pl += __shfl_xor_sync(0xffffffffu, pl, 1);
            pr += __shfl_xor_sync(0xffffffffu, pr, 1);
            if ((tx & 1) == 0 && row < nrows) {
                g_el[row * NH + (tx >> 1)] = pl;
                g_er[row * NH + (tx >> 1)] = pr;
            }
        } else if (row < nrows) {
            float im = g_invm[row];
            float4 o0 = *(const float4*)&out[(size_t)row * 128 + tx * 8];
            float4 o1 = *(const float4*)&out[(size_t)row * 128 + tx * 8 + 4];
            o0.x += c[0] * im; o0.y += c[1] * im; o0.z += c[2] * im; o0.w += c[3] * im;
            o1.x += c[4] * im; o1.y += c[5] * im; o1.z += c[6] * im; o1.w += c[7] * im;
            *(float4*)&out[(size_t)row * 128 + tx * 8]     = o0;
            *(float4*)&out[(size_t)row * 128 + tx * 8 + 4] = o1;
        }
    }
}

// ---------------- sort-by-dst: histogram / scan / permute ----------------
__global__ void hist_kernel(const int* __restrict__ dst, int E) {
    int e = blockIdx.x * blockDim.x + threadIdx.x;
    if (e < E) atomicAdd(&g_cnt[dst[e]], 1);
}

__global__ void scan_kernel(int N, int E) {   // single block, 1024 threads
    __shared__ int s[1024];
    int tid = threadIdx.x;
    int per = (N + 1023) >> 10;
    int beg = tid * per, fin = beg + per; if (fin > N) fin = N; if (beg > N) beg = N;
    int sum = 0;
    for (int i = beg; i < fin; i++) sum += g_cnt[i];
    s[tid] = sum;
    __syncthreads();
    for (int off = 1; off < 1024; off <<= 1) {
        int u = (tid >= off) ? s[tid - off] : 0;
        __syncthreads();
        s[tid] += u;
        __syncthreads();
    }
    int run = s[tid] - sum;                   // exclusive base for this chunk
    for (int i = beg; i < fin; i++) {
        int c = g_cnt[i];
        g_off[i] = run;
        g_cur[i] = run;
        run += c;
    }
    if (tid == 0) g_off[N] = E;
}

__global__ void permute_kernel(const int* __restrict__ src, const int* __restrict__ dst, int E) {
    int e = blockIdx.x * blockDim.x + threadIdx.x;
    if (e >= E) return;
    int d = dst[e];
    int pos = atomicAdd(&g_cur[d], 1);
    g_pse[pos] = make_int2(src[e], e);
}

// ---------------- node aggregation: one warp per node, atomic-free ----------------
// out[n] = (Σ ex·hf[s]) / denom + bias + hf[n]/(deg+1) + b_e·(deg>0)
// Sagg[n] = Σ efeat[e];  invm[n] = 1/max(deg,1)        (he term added by gemm2)
__global__ __launch_bounds__(256)
void node_agg_kernel(const float4* __restrict__ efeat4, float* __restrict__ out,
                     const float4* __restrict__ bias4, const float4* __restrict__ be4, int N) {
    int n = ((blockIdx.x * blockDim.x + threadIdx.x) >> 5);
    if (n >= N) return;
    int lane = threadIdx.x & 31;
    int hh = lane & 7;
    int start = g_off[n], end = g_off[n + 1];
    int deg = end - start;
    float er_n = g_er[n * NH + hh];
    const float4* hf4 = (const float4*)g_hf;

    float4 aS = make_float4(0.f, 0.f, 0.f, 0.f);
    float4 aO = make_float4(0.f, 0.f, 0.f, 0.f);
    float dacc = 0.f;

    int p = start;
    for (; p + 2 <= end; p += 2) {
        int2 pa = g_pse[p], pb = g_pse[p + 1];
        float4 e0 = efeat4[(size_t)pa.y * 32 + lane];
        float4 e1 = efeat4[(size_t)pb.y * 32 + lane];
        float4 h0 = hf4[(size_t)pa.x * 32 + lane];
        float4 h1 = hf4[(size_t)pb.x * 32 + lane];
        float x0 = __expf(leaky02(g_el[pa.x * NH + hh] + er_n));
        float x1 = __expf(leaky02(g_el[pb.x * NH + hh] + er_n));
        dacc += x0 + x1;
        float a0 = __shfl_sync(0xffffffffu, x0, lane >> 2);
        float a1 = __shfl_sync(0xffffffffu, x1, lane >> 2);
        aS.x += e0.x + e1.x; aS.y += e0.y + e1.y; aS.z += e0.z + e1.z; aS.w += e0.w + e1.w;
        aO.x += a0 * h0.x + a1 * h1.x;
        aO.y += a0 * h0.y + a1 * h1.y;
        aO.z += a0 * h0.z + a1 * h1.z;
        aO.w += a0 * h0.w + a1 * h1.w;
    }
    if (p < end) {
        int2 pa = g_pse[p];
        float4 e0 = efeat4[(size_t)pa.y * 32 + lane];
        float4 h0 = hf4[(size_t)pa.x * 32 + lane];
        float x0 = __expf(leaky02(g_el[pa.x * NH + hh] + er_n));
        dacc += x0;
        float a0 = __shfl_sync(0xffffffffu, x0, lane >> 2);
        aS.x += e0.x; aS.y += e0.y; aS.z += e0.z; aS.w += e0.w;
        aO.x += a0 * h0.x; aO.y += a0 * h0.y; aO.z += a0 * h0.z; aO.w += a0 * h0.w;
    }

    float den = __shfl_sync(0xffffffffu, dacc, lane >> 2);   // denom for head (lane>>2)
    float invden = den > 0.f ? 1.f / den : 0.f;
    float deg_f = (float)deg;
    float inv1 = 1.f / (deg_f + 1.f);
    float gate = deg > 0 ? 1.f : 0.f;

    float4 hn = hf4[(size_t)n * 32 + lane];
    float4 b  = bias4[lane];
    float4 be = be4[lane];
    float4 o;
    o.x = aO.x * invden + b.x + hn.x * inv1 + be.x * gate;
    o.y = aO.y * invden + b.y + hn.y * inv1 + be.y * gate;
    o.z = aO.z * invden + b.z + hn.z * inv1 + be.z * gate;
    o.w = aO.w * invden + b.w + hn.w * inv1 + be.w * gate;
    ((float4*)out)[(size_t)n * 32 + lane] = o;
    ((float4*)g_Sagg)[(size_t)n * 32 + lane] = aS;
    if (lane == 0) g_invm[n] = 1.f / fmaxf(deg_f, 1.f);
}

extern "C" void kernel_launch(void* const* d_in, const int* in_sizes, int n_in,
                              void* d_out, int out_size) {
    const float* nfeat  = (const float*)d_in[0];
    const float* efeat  = (const float*)d_in[1];
    const int*   src    = (const int*)d_in[2];
    const int*   dst    = (const int*)d_in[3];
    const float* W_fc   = (const float*)d_in[4];
    const float* attn_l = (const float*)d_in[5];
    const float* attn_r = (const float*)d_in[6];
    const float* bias   = (const float*)d_in[7];
    const float* W_e    = (const float*)d_in[8];
    const float* b_e    = (const float*)d_in[9];
    float* out = (float*)d_out;

    int N = in_sizes[0] / 128;
    int E = in_sizes[2];

    float* d_hf;   cudaGetSymbolAddress((void**)&d_hf,   g_hf);
    float* d_Sagg; cudaGetSymbolAddress((void**)&d_Sagg, g_Sagg);
    int*   d_cnt;  cudaGetSymbolAddress((void**)&d_cnt,  g_cnt);

    cudaMemsetAsync(d_cnt, 0, (size_t)N * sizeof(int));

    hist_kernel<<<(E + 255) / 256, 256>>>(dst, E);
    gemm_kernel<<<(N + 127) / 128, 256>>>(nfeat, W_fc, d_hf, N, 0, attn_l, attn_r);
    scan_kernel<<<1, 1024>>>(N, E);
    permute_kernel<<<(E + 255) / 256, 256>>>(src, dst, E);

    node_agg_kernel<<<(N + 7) / 8, 256>>>((const float4*)efeat, out,
                                          (const float4*)bias, (const float4*)b_e, N);

    gemm_kernel<<<(N + 127) / 128, 256>>>(d_Sagg, W_e, out, N, 1, nullptr, nullptr);
}

// round 8
// speedup vs baseline: 1.0171x; 1.0171x over previous
#include <cuda_runtime.h>

#define N_MAX 50000
#define E_MAX 800000
#define HD 128
#define NH 8

// ---- scratch (device globals; no allocation allowed) ----
__device__ float g_hf[N_MAX * HD];      // nfeat @ W_fc
__device__ float g_el[N_MAX * NH];
__device__ float g_er[N_MAX * NH];
__device__ float g_Sagg[N_MAX * HD];    // segment_sum(efeat)
__device__ float g_invm[N_MAX];         // 1/max(deg,1)
__device__ int   g_cnt[N_MAX];          // dst histogram
__device__ int   g_off[N_MAX + 1];      // CSR offsets (immutable)
__device__ int   g_cur[N_MAX];          // mutable cursor for permute
__device__ int2  g_pse[E_MAX];          // (src, edge_id) grouped by dst

// packed f32x2 helpers (FFMA2 — PTX-only path on sm_103a)
__device__ __forceinline__ unsigned long long pack2(float lo, float hi) {
    unsigned long long r;
    asm("mov.b64 %0, {%1, %2};" : "=l"(r) : "r"(__float_as_uint(lo)), "r"(__float_as_uint(hi)));
    return r;
}
__device__ __forceinline__ void fma2(unsigned long long& acc, unsigned long long a, unsigned long long b) {
    asm("fma.rn.f32x2 %0, %1, %2, %0;" : "+l"(acc) : "l"(a), "l"(b));
}
__device__ __forceinline__ void unpack2(unsigned long long v, float& lo, float& hi) {
    unsigned int l, h;
    asm("mov.b64 {%0, %1}, %2;" : "=r"(l), "=r"(h) : "l"(v));
    lo = __uint_as_float(l); hi = __uint_as_float(h);
}

__device__ __forceinline__ float leaky02(float x) { return x > 0.f ? x : 0.2f * x; }

// ---------------- GEMM: 128x128 block tile, 8x8 per thread ----------------
// mode 0: out = A@W, plus el/er head reductions.
// mode 1: fused finalize: out[row] += (A@W)[row] * g_invm[row]   (out preloaded)
#define KC 32
__global__ __launch_bounds__(256, 2)
void gemm_kernel(const float* __restrict__ A, const float* __restrict__ W,
                 float* __restrict__ out, int nrows, int mode,
                 const float* __restrict__ attn_l, const float* __restrict__ attn_r) {
    __shared__ float Ws[KC][128];
    __shared__ float As[128][KC + 4];
    int t = threadIdx.x;
    int tx = t & 15;
    int ty = t >> 4;
    int rbase = blockIdx.x * 128;

    unsigned long long acc[8][4];
#pragma unroll
    for (int i = 0; i < 8; i++)
#pragma unroll
        for (int j = 0; j < 4; j++) acc[i][j] = 0ull;

    for (int kc = 0; kc < 4; kc++) {
#pragma unroll
        for (int i = 0; i < 4; i++) {
            int lin = i * 256 + t;
            int r = lin >> 5, c4 = lin & 31;
            *((float4*)&Ws[r][c4 * 4]) = ((const float4*)W)[(kc * 32 + r) * 32 + c4];
        }
#pragma unroll
        for (int i = 0; i < 4; i++) {
            int lin = i * 256 + t;
            int r = lin >> 3, k4 = lin & 7;
            int row = rbase + r;
            float4 v = (row < nrows) ? ((const float4*)A)[(size_t)row * 32 + kc * 8 + k4]
                                     : make_float4(0.f, 0.f, 0.f, 0.f);
            *((float4*)&As[r][k4 * 4]) = v;
        }
        __syncthreads();
#pragma unroll
        for (int k = 0; k < KC; k++) {
            unsigned long long w2[4];
#pragma unroll
            for (int j = 0; j < 4; j++)
                w2[j] = *(const unsigned long long*)&Ws[k][tx * 8 + j * 2];
#pragma unroll
            for (int i = 0; i < 8; i++) {
                float a = As[ty * 8 + i][k];
                unsigned long long aa = pack2(a, a);
#pragma unroll
                for (int j = 0; j < 4; j++) fma2(acc[i][j], aa, w2[j]);
            }
        }
        __syncthreads();
    }

    float al[8], ar[8];
    if (mode == 0) {
#pragma unroll
        for (int j = 0; j < 8; j++) { al[j] = attn_l[tx * 8 + j]; ar[j] = attn_r[tx * 8 + j]; }
    }

#pragma unroll
    for (int i = 0; i < 8; i++) {
        int row = rbase + ty * 8 + i;
        float c[8];
#pragma unroll
        for (int j = 0; j < 4; j++) unpack2(acc[i][j], c[2 * j], c[2 * j + 1]);
        if (mode == 0) {
            if (row < nrows) {
                *(float4*)&out[(size_t)row * 128 + tx * 8]     = make_float4(c[0], c[1], c[2], c[3]);
                *(float4*)&out[(size_t)row * 128 + tx * 8 + 4] = make_float4(c[4], c[5], c[6], c[7]);
            }
            float pl = 0.f, pr = 0.f;
#pragma unroll
            for (int j = 0; j < 8; j++) { pl += c[j] * al[j]; pr += c[j] * ar[j]; }
            pl += __shfl_xor_sync(0xffffffffu, pl, 1);
            pr += __shfl_xor_sync(0xffffffffu, pr, 1);
            if ((tx & 1) == 0 && row < nrows) {
                g_el[row * NH + (tx >> 1)] = pl;
                g_er[row * NH + (tx >> 1)] = pr;
            }
        } else if (row < nrows) {
            float im = g_invm[row];
            float4 o0 = *(const float4*)&out[(size_t)row * 128 + tx * 8];
            float4 o1 = *(const float4*)&out[(size_t)row * 128 + tx * 8 + 4];
            o0.x += c[0] * im; o0.y += c[1] * im; o0.z += c[2] * im; o0.w += c[3] * im;
            o1.x += c[4] * im; o1.y += c[5] * im; o1.z += c[6] * im; o1.w += c[7] * im;
            *(float4*)&out[(size_t)row * 128 + tx * 8]     = o0;
            *(float4*)&out[(size_t)row * 128 + tx * 8 + 4] = o1;
        }
    }
}

// ---------------- sort-by-dst: histogram / scan / permute ----------------
__global__ void hist_kernel(const int* __restrict__ dst, int E) {
    int e = blockIdx.x * blockDim.x + threadIdx.x;
    if (e < E) atomicAdd(&g_cnt[__ldcs(&dst[e])], 1);
}

__global__ void scan_kernel(int N, int E) {   // single block, 1024 threads
    __shared__ int s[1024];
    int tid = threadIdx.x;
    int per = (N + 1023) >> 10;
    int beg = tid * per, fin = beg + per; if (fin > N) fin = N; if (beg > N) beg = N;
    int sum = 0;
#pragma unroll 4
    for (int i = beg; i < fin; i++) sum += g_cnt[i];
    s[tid] = sum;
    __syncthreads();
    for (int off = 1; off < 1024; off <<= 1) {
        int u = (tid >= off) ? s[tid - off] : 0;
        __syncthreads();
        s[tid] += u;
        __syncthreads();
    }
    int run = s[tid] - sum;                   // exclusive base for this chunk
    for (int i = beg; i < fin; i++) {
        int c = g_cnt[i];
        g_off[i] = run;
        g_cur[i] = run;
        run += c;
    }
    if (tid == 0) g_off[N] = E;
}

__global__ void permute_kernel(const int* __restrict__ src, const int* __restrict__ dst, int E) {
    int e = blockIdx.x * blockDim.x + threadIdx.x;
    if (e >= E) return;
    int d = __ldcs(&dst[e]);
    int pos = atomicAdd(&g_cur[d], 1);
    g_pse[pos] = make_int2(__ldcs(&src[e]), e);
}

// ---------------- node aggregation: one warp per node, atomic-free ----------------
// out[n] = (Σ ex·hf[s]) / denom + bias + hf[n]/(deg+1) + b_e·(deg>0)
// Sagg[n] = Σ efeat[e];  invm[n] = 1/max(deg,1)        (he term added by gemm2)
// Streamed data (efeat, pse) uses evict-first loads so the hot hf/el tables
// stay L2-resident across their ~16 gather touches.
__global__ __launch_bounds__(256)
void node_agg_kernel(const float4* __restrict__ efeat4, float* __restrict__ out,
                     const float4* __restrict__ bias4, const float4* __restrict__ be4, int N) {
    int n = ((blockIdx.x * blockDim.x + threadIdx.x) >> 5);
    if (n >= N) return;
    int lane = threadIdx.x & 31;
    int h = lane >> 2;                        // head this lane's 4 output floats belong to
    int start = g_off[n], end = g_off[n + 1];
    int deg = end - start;
    float er_n = g_er[n * NH + h];
    const float4* hf4 = (const float4*)g_hf;

    float4 aS = make_float4(0.f, 0.f, 0.f, 0.f);
    float4 aO = make_float4(0.f, 0.f, 0.f, 0.f);
    float dacc = 0.f;                         // this head's denom (replicated per quad)

    int p = start;
#pragma unroll 1
    for (; p + 4 <= end; p += 4) {
        int2 pe[4];
        float4 ev[4], hv[4];
        float x[4];
#pragma unroll
        for (int q = 0; q < 4; q++) pe[q] = __ldcs(&g_pse[p + q]);
#pragma unroll
        for (int q = 0; q < 4; q++) ev[q] = __ldcs(&efeat4[(size_t)pe[q].y * 32 + lane]);
#pragma unroll
        for (int q = 0; q < 4; q++) hv[q] = hf4[(size_t)pe[q].x * 32 + lane];
#pragma unroll
        for (int q = 0; q < 4; q++)
            x[q] = __expf(leaky02(g_el[pe[q].x * NH + h] + er_n));
#pragma unroll
        for (int q = 0; q < 4; q++) {
            dacc += x[q];
            aS.x += ev[q].x; aS.y += ev[q].y; aS.z += ev[q].z; aS.w += ev[q].w;
            aO.x += x[q] * hv[q].x; aO.y += x[q] * hv[q].y;
            aO.z += x[q] * hv[q].z; aO.w += x[q] * hv[q].w;
        }
    }
    for (; p < end; p++) {
        int2 pa = __ldcs(&g_pse[p]);
        float4 e0 = __ldcs(&efeat4[(size_t)pa.y * 32 + lane]);
        float4 h0 = hf4[(size_t)pa.x * 32 + lane];
        float x0 = __expf(leaky02(g_el[pa.x * NH + h] + er_n));
        dacc += x0;
        aS.x += e0.x; aS.y += e0.y; aS.z += e0.z; aS.w += e0.w;
        aO.x += x0 * h0.x; aO.y += x0 * h0.y; aO.z += x0 * h0.z; aO.w += x0 * h0.w;
    }

    float invden = dacc > 0.f ? 1.f / dacc : 0.f;
    float deg_f = (float)deg;
    float inv1 = 1.f / (deg_f + 1.f);
    float gate = deg > 0 ? 1.f : 0.f;

    float4 hn = hf4[(size_t)n * 32 + lane];
    float4 b  = bias4[lane];
    float4 be = be4[lane];
    float4 o;
    o.x = aO.x * invden + b.x + hn.x * inv1 + be.x * gate;
    o.y = aO.y * invden + b.y + hn.y * inv1 + be.y * gate;
    o.z = aO.z * invden + b.z + hn.z * inv1 + be.z * gate;
    o.w = aO.w * invden + b.w + hn.w * inv1 + be.w * gate;
    ((float4*)out)[(size_t)n * 32 + lane] = o;
    ((float4*)g_Sagg)[(size_t)n * 32 + lane] = aS;
    if (lane == 0) g_invm[n] = 1.f / fmaxf(deg_f, 1.f);
}

extern "C" void kernel_launch(void* const* d_in, const int* in_sizes, int n_in,
                              void* d_out, int out_size) {
    const float* nfeat  = (const float*)d_in[0];
    const float* efeat  = (const float*)d_in[1];
    const int*   src    = (const int*)d_in[2];
    const int*   dst    = (const int*)d_in[3];
    const float* W_fc   = (const float*)d_in[4];
    const float* attn_l = (const float*)d_in[5];
    const float* attn_r = (const float*)d_in[6];
    const float* bias   = (const float*)d_in[7];
    const float* W_e    = (const float*)d_in[8];
    const float* b_e    = (const float*)d_in[9];
    float* out = (float*)d_out;

    int N = in_sizes[0] / 128;
    int E = in_sizes[2];

    float* d_hf;   cudaGetSymbolAddress((void**)&d_hf,   g_hf);
    float* d_Sagg; cudaGetSymbolAddress((void**)&d_Sagg, g_Sagg);
    int*   d_cnt;  cudaGetSymbolAddress((void**)&d_cnt,  g_cnt);

    cudaMemsetAsync(d_cnt, 0, (size_t)N * sizeof(int));

    hist_kernel<<<(E + 255) / 256, 256>>>(dst, E);
    gemm_kernel<<<(N + 127) / 128, 256>>>(nfeat, W_fc, d_hf, N, 0, attn_l, attn_r);
    scan_kernel<<<1, 1024>>>(N, E);
    permute_kernel<<<(E + 255) / 256, 256>>>(src, dst, E);

    node_agg_kernel<<<(N + 7) / 8, 256>>>((const float4*)efeat, out,
                                          (const float4*)bias, (const float4*)b_e, N);

    gemm_kernel<<<(N + 127) / 128, 256>>>(d_Sagg, W_e, out, N, 1, nullptr, nullptr);
}